// round 14
// baseline (speedup 1.0000x reference)
#include <cuda_runtime.h>
#include <cstdint>

// Problem constants
#define B   32
#define C   256
#define H   56
#define W   56
#define OH  28
#define OW  28
#define CO  256           // outputs per half
#define NW  8             // 256 bits -> 8 uint32 words
#define NPX (OH*OW)       // 784 pixels per (b, half) plane
#define NCHUNK 25         // ceil(784/32)
#define NELEM_PER_C (B*H*W)  // 100352

// -------- device scratch (no allocations allowed) --------
__device__ float    g_partial[C][B][2];          // per (channel, batch): sum, sumsq
__device__ float    g_lo[C];                     // binarize window: +1 iff lo <= v <= hi
__device__ float    g_hi[C];
__device__ int      g_fast;                      // 1 if all gamma > 0 (lo-only compare)
__device__ unsigned g_wpack[2*CO][NW];           // rows 0..255 = w1, 256..511 = w2
__device__ unsigned g_count;                     // stats-block arrival counter (reset each run)

// ============================================================
// Kernel 1: stats partials (one warp per (b,c) plane) + weight pack
// + LAST-BLOCK threshold finalize.  (unchanged from round 12)
// grid 1088: blocks 0..1023 stats, 1024..1087 wpack.
// ============================================================
__global__ __launch_bounds__(256) void stats_wpack_kernel(const float* __restrict__ x,
                                                          const float* __restrict__ w1,
                                                          const float* __restrict__ w2,
                                                          const float* __restrict__ gamma,
                                                          const float* __restrict__ beta) {
    int lane = threadIdx.x & 31;
    if (blockIdx.x >= 1024) {
        int warp = ((blockIdx.x - 1024) * 256 + threadIdx.x) >> 5;   // 0..511
        const float* w = (warp < CO) ? (w1 + (size_t)warp * C)
                                     : (w2 + (size_t)(warp - CO) * C);
        #pragma unroll
        for (int j = 0; j < NW; j++) {
            float v = w[j * 32 + lane];
            unsigned m = __ballot_sync(0xffffffffu, v >= 0.f);
            if (lane == 0) g_wpack[warp][j] = m;
        }
        return;
    }
    int wid = (blockIdx.x * 256 + threadIdx.x) >> 5;  // plane 0..8191
    int b = wid >> 8, c = wid & 255;
    const float4* p = reinterpret_cast<const float4*>(x + ((size_t)b * C + c) * (H * W));
    float s0 = 0.f, s1 = 0.f, q0 = 0.f, q1 = 0.f;
    #pragma unroll 8
    for (int it = 0; it < 24; it++) {
        float4 v = p[lane + it * 32];
        s0 += v.x + v.y;
        s1 += v.z + v.w;
        q0 += v.x * v.x + v.y * v.y;
        q1 += v.z * v.z + v.w * v.w;
    }
    if (lane < 16) {
        float4 v = p[lane + 768];
        s0 += v.x + v.y;
        s1 += v.z + v.w;
        q0 += v.x * v.x + v.y * v.y;
        q1 += v.z * v.z + v.w * v.w;
    }
    float s = s0 + s1, q = q0 + q1;
    #pragma unroll
    for (int o = 16; o > 0; o >>= 1) {
        s += __shfl_down_sync(0xffffffffu, s, o);
        q += __shfl_down_sync(0xffffffffu, q, o);
    }
    if (lane == 0) {
        g_partial[c][b][0] = s;
        g_partial[c][b][1] = q;
    }

    __threadfence();
    __shared__ int is_last;
    if (threadIdx.x == 0)
        is_last = (atomicAdd(&g_count, 1u) == 1023u);
    __syncthreads();
    if (!is_last) return;

    {
        int c2 = threadIdx.x;
        float ss = 0.f, sq = 0.f;
        #pragma unroll
        for (int k = 0; k < B; k++) { ss += g_partial[c2][k][0]; sq += g_partial[c2][k][1]; }
        const float N = (float)NELEM_PER_C;
        float mean = ss / N;
        float var  = sq / N - mean * mean;
        if (var < 0.f) var = 0.f;
        float inv = rsqrtf(var + 1e-5f);
        float g = gamma[c2], bt = beta[c2];
        const float INF = __int_as_float(0x7f800000);
        float lo, hi;
        if (g > 0.f)      { lo = mean - bt / (inv * g); hi =  INF; }
        else if (g < 0.f) { hi = mean - bt / (inv * g); lo = -INF; }
        else if (bt >= 0.f) { lo = -INF; hi =  INF; }
        else                { lo =  INF; hi = -INF; }
        g_lo[c2] = lo;
        g_hi[c2] = hi;

        __shared__ int sflag;
        if (threadIdx.x == 0) sflag = 1;
        __syncthreads();
        unsigned warp_ok = __ballot_sync(0xffffffffu, g > 0.f);
        if ((threadIdx.x & 31) == 0 && warp_ok != 0xffffffffu) atomicAnd(&sflag, 0);
        __syncthreads();
        if (threadIdx.x == 0) {
            g_fast = sflag;
            g_count = 0;          // reset for next graph replay
        }
    }
}

// ============================================================
// Kernel 2 (FUSED, FLAT-PIXEL): binarize+pack, then XNOR-popcount GEMM.
// grid (25, B, 2): block = 32-pixel chunk of one (b, half) plane.
// lane = flat pixel p = chunk*32+lane (oh=p/28, ow=p%28):
//   - all 32 lanes active in both phases (was 28/32)
//   - warp stores are 128 contiguous bytes (full 32B sectors -> no RMW)
// Structure (8 warps, pack->barrier->gemm, plain weight stage) = r12 proven.
// ============================================================
__global__ __launch_bounds__(256) void fused_kernel(const float* __restrict__ x,
                                                    float* __restrict__ out) {
    int chunk = blockIdx.x, b = blockIdx.y, half = blockIdx.z;
    int j    = threadIdx.x >> 5;
    int lane = threadIdx.x & 31;

    __shared__ uint4 sa4[32 * NW / 4];   // 1 KB packed activations (32 px)
    __shared__ uint4 sw4[CO * NW / 4];   // 8 KB packed weights (this half)
    unsigned* sa = reinterpret_cast<unsigned*>(sa4);

    int p  = chunk * 32 + lane;
    int pv = p < NPX ? p : NPX - 1;      // clamp tail lanes (stores masked later)
    int oh = pv / OW;
    int ow = pv - oh * OW;
    int h  = 2 * oh + half;

    // ---- Phase A: binarize + register-pack ----
    {
        const size_t cstep = (size_t)H * W;
        const float* base = x + (((size_t)b * C + j * 32) * H + h) * W;
        unsigned bits = 0;
        if (g_fast) {
            float lo_mine = g_lo[j * 32 + lane];      // one value per lane
            #pragma unroll 8
            for (int r = 0; r < 32; r++) {
                float2 v = __ldcg(reinterpret_cast<const float2*>(base + r * cstep) + ow);
                float val = half ? v.y : v.x;
                float lo_r = __shfl_sync(0xffffffffu, lo_mine, r);
                bits |= (val >= lo_r ? 1u : 0u) << r;
            }
        } else {
            #pragma unroll 8
            for (int r = 0; r < 32; r++) {
                int c = j * 32 + r;
                float2 v = __ldcg(reinterpret_cast<const float2*>(base + r * cstep) + ow);
                float val = half ? v.y : v.x;
                bool pred = (val >= g_lo[c]) && (val <= g_hi[c]);
                bits |= (pred ? 1u : 0u) << r;
            }
        }
        sa[lane * NW + j] = bits;        // all 32 lanes
    }

    // ---- stage weights (plain loads, r12 style) ----
    {
        const uint4* wsrc = reinterpret_cast<const uint4*>(&g_wpack[half * CO][0]);
        #pragma unroll
        for (int i = 0; i < (CO * NW / 4) / 256; i++)
            sw4[i * 256 + threadIdx.x] = wsrc[i * 256 + threadIdx.x];
    }
    __syncthreads();

    // ---- Phase B: popcount GEMM, full-line coalesced stores ----
    uint4 av0 = sa4[lane * 2 + 0];
    uint4 av1 = sa4[lane * 2 + 1];
    unsigned a0 = av0.x, a1 = av0.y, a2 = av0.z, a3 = av0.w;
    unsigned a4 = av1.x, a5 = av1.y, a6 = av1.z, a7 = av1.w;

    bool valid = (p < NPX);
    float* op = out + ((size_t)b * 2 * CO + (size_t)half * CO) * NPX + p;
    #pragma unroll 8
    for (int oo = 0; oo < CO / 8; oo++) {
        int o = oo * 8 + j;
        uint4 wv0 = sw4[o * 2 + 0];
        uint4 wv1 = sw4[o * 2 + 1];
        int s = __popc(a0 ^ wv0.x) + __popc(a1 ^ wv0.y)
              + __popc(a2 ^ wv0.z) + __popc(a3 ^ wv0.w)
              + __popc(a4 ^ wv1.x) + __popc(a5 ^ wv1.y)
              + __popc(a6 ^ wv1.z) + __popc(a7 ^ wv1.w);
        if (valid) op[(size_t)o * NPX] = (float)(C - 2 * s);
    }
}

// ============================================================
extern "C" void kernel_launch(void* const* d_in, const int* in_sizes, int n_in,
                              void* d_out, int out_size) {
    const float* x     = (const float*)d_in[0];
    const float* gamma = (const float*)d_in[1];
    const float* beta  = (const float*)d_in[2];
    const float* w1    = (const float*)d_in[3];
    const float* w2    = (const float*)d_in[4];
    float* out = (float*)d_out;

    stats_wpack_kernel<<<1088, 256>>>(x, w1, w2, gamma, beta);
    fused_kernel<<<dim3(NCHUNK, B, 2), 256>>>(x, out);
}

// round 15
// speedup vs baseline: 1.0704x; 1.0704x over previous
#include <cuda_runtime.h>
#include <cstdint>

// Problem constants
#define B   32
#define C   256
#define H   56
#define W   56
#define OH  28
#define OW  28
#define CO  256           // outputs per half
#define NW  8             // 256 bits -> 8 uint32 words
#define NELEM_PER_C (B*H*W)  // 100352

// -------- device scratch (no allocations allowed) --------
__device__ float    g_partial[C][B][2];          // per (channel, batch): sum, sumsq
__device__ float    g_lo[C];                     // binarize window: +1 iff lo <= v <= hi
__device__ float    g_hi[C];
__device__ int      g_fast;                      // 1 if all gamma > 0 (lo-only compare)
__device__ unsigned g_wpack[2*CO][NW];           // rows 0..255 = w1, 256..511 = w2
__device__ unsigned g_count;                     // stats-block arrival counter (reset each run)

// ============================================================
// Kernel 1: stats partials (one warp per (b,c) plane) + weight pack
// + LAST-BLOCK threshold finalize.  (r12 structure + PDL trigger)
// grid 1088: blocks 0..1023 stats, 1024..1087 wpack.
// ============================================================
__global__ __launch_bounds__(256) void stats_wpack_kernel(const float* __restrict__ x,
                                                          const float* __restrict__ w1,
                                                          const float* __restrict__ w2,
                                                          const float* __restrict__ gamma,
                                                          const float* __restrict__ beta) {
    int lane = threadIdx.x & 31;
    if (blockIdx.x >= 1024) {
        int warp = ((blockIdx.x - 1024) * 256 + threadIdx.x) >> 5;   // 0..511
        const float* w = (warp < CO) ? (w1 + (size_t)warp * C)
                                     : (w2 + (size_t)(warp - CO) * C);
        #pragma unroll
        for (int j = 0; j < NW; j++) {
            float v = w[j * 32 + lane];
            unsigned m = __ballot_sync(0xffffffffu, v >= 0.f);
            if (lane == 0) g_wpack[warp][j] = m;
        }
        return;   // early exit counts as PDL arrival for this block
    }
    int wid = (blockIdx.x * 256 + threadIdx.x) >> 5;  // plane 0..8191
    int b = wid >> 8, c = wid & 255;
    const float4* p = reinterpret_cast<const float4*>(x + ((size_t)b * C + c) * (H * W));
    float s0 = 0.f, s1 = 0.f, q0 = 0.f, q1 = 0.f;
    #pragma unroll 8
    for (int it = 0; it < 24; it++) {
        float4 v = p[lane + it * 32];
        s0 += v.x + v.y;
        s1 += v.z + v.w;
        q0 += v.x * v.x + v.y * v.y;
        q1 += v.z * v.z + v.w * v.w;
    }
    if (lane < 16) {
        float4 v = p[lane + 768];
        s0 += v.x + v.y;
        s1 += v.z + v.w;
        q0 += v.x * v.x + v.y * v.y;
        q1 += v.z * v.z + v.w * v.w;
    }
    float s = s0 + s1, q = q0 + q1;
    #pragma unroll
    for (int o = 16; o > 0; o >>= 1) {
        s += __shfl_down_sync(0xffffffffu, s, o);
        q += __shfl_down_sync(0xffffffffu, q, o);
    }
    if (lane == 0) {
        g_partial[c][b][0] = s;
        g_partial[c][b][1] = q;
    }

    // Let the dependent fused kernel start scheduling its blocks now.
    // (cudaGridDependencySynchronize in fused still waits for FULL completion
    //  of this grid, so the finalize below stays ordered before any consumer.)
    cudaTriggerProgrammaticLaunchCompletion();

    // ---- last-arriving stats block finalizes thresholds ----
    __threadfence();
    __shared__ int is_last;
    if (threadIdx.x == 0)
        is_last = (atomicAdd(&g_count, 1u) == 1023u);
    __syncthreads();
    if (!is_last) return;

    {
        int c2 = threadIdx.x;                     // 256 threads = 256 channels
        float ss = 0.f, sq = 0.f;
        #pragma unroll
        for (int k = 0; k < B; k++) { ss += g_partial[c2][k][0]; sq += g_partial[c2][k][1]; }
        const float N = (float)NELEM_PER_C;
        float mean = ss / N;
        float var  = sq / N - mean * mean;
        if (var < 0.f) var = 0.f;
        float inv = rsqrtf(var + 1e-5f);
        float g = gamma[c2], bt = beta[c2];
        const float INF = __int_as_float(0x7f800000);
        float lo, hi;
        if (g > 0.f)      { lo = mean - bt / (inv * g); hi =  INF; }
        else if (g < 0.f) { hi = mean - bt / (inv * g); lo = -INF; }
        else if (bt >= 0.f) { lo = -INF; hi =  INF; }
        else                { lo =  INF; hi = -INF; }
        g_lo[c2] = lo;
        g_hi[c2] = hi;

        __shared__ int sflag;
        if (threadIdx.x == 0) sflag = 1;
        __syncthreads();
        unsigned warp_ok = __ballot_sync(0xffffffffu, g > 0.f);
        if ((threadIdx.x & 31) == 0 && warp_ok != 0xffffffffu) atomicAnd(&sflag, 0);
        __syncthreads();
        if (threadIdx.x == 0) {
            g_fast = sflag;
            g_count = 0;          // reset for next graph replay
        }
    }
}

// ============================================================
// Kernel 2 (FUSED): binarize+pack into smem, then XNOR-popcount GEMM.
// EXACT r12 structure (best measured: 37.7us): grid (OH, B, 2) oh-fastest,
// no launch_bounds cap, plain weight stage, __ldcg x loads.
// Only addition: gridDependencySynchronize() for the PDL launch.
// ============================================================
__global__ __launch_bounds__(256) void fused_kernel(const float* __restrict__ x,
                                                    float* __restrict__ out) {
    // Wait for stats_wpack_kernel's memory to be fully visible (PDL).
    cudaGridDependencySynchronize();

    int oh = blockIdx.x, b = blockIdx.y, half = blockIdx.z;
    int j    = threadIdx.x >> 5;
    int lane = threadIdx.x & 31;
    int h = 2 * oh + half;

    __shared__ uint4 sa4[OW * NW / 4];   // 896 B packed activations
    __shared__ uint4 sw4[CO * NW / 4];   // 8 KB packed weights (this half)
    unsigned* sa = reinterpret_cast<unsigned*>(sa4);

    // ---- Phase A: binarize + register-pack (LDGs first) ----
    {
        const size_t rowstep = (size_t)H * W;
        int k = lane < OW ? lane : OW - 1;            // clamp so all lanes can shfl
        const float* base = x + (((size_t)b * C + j * 32) * H + h) * W;
        unsigned bits = 0;
        if (g_fast) {
            float lo_mine = g_lo[j * 32 + lane];      // one value per lane
            #pragma unroll 8
            for (int r = 0; r < 32; r++) {
                float2 v = __ldcg(reinterpret_cast<const float2*>(base + r * rowstep) + k);
                float val = half ? v.y : v.x;
                float lo_r = __shfl_sync(0xffffffffu, lo_mine, r);
                bits |= (val >= lo_r ? 1u : 0u) << r;
            }
        } else {
            #pragma unroll 8
            for (int r = 0; r < 32; r++) {
                int c = j * 32 + r;
                float2 v = __ldcg(reinterpret_cast<const float2*>(base + r * rowstep) + k);
                float val = half ? v.y : v.x;
                bool pred = (val >= g_lo[c]) && (val <= g_hi[c]);
                bits |= (pred ? 1u : 0u) << r;
            }
        }
        if (lane < OW) sa[lane * NW + j] = bits;
    }

    // ---- stage weights (L2-hot after first wave) ----
    {
        const uint4* wsrc = reinterpret_cast<const uint4*>(&g_wpack[half * CO][0]);
        #pragma unroll
        for (int i = 0; i < (CO * NW / 4) / 256; i++)
            sw4[i * 256 + threadIdx.x] = wsrc[i * 256 + threadIdx.x];
    }
    __syncthreads();

    // ---- Phase B: popcount GEMM (vector LDS) ----
    if (lane >= OW) return;

    uint4 av0 = sa4[lane * 2 + 0];
    uint4 av1 = sa4[lane * 2 + 1];
    unsigned a0 = av0.x, a1 = av0.y, a2 = av0.z, a3 = av0.w;
    unsigned a4 = av1.x, a5 = av1.y, a6 = av1.z, a7 = av1.w;

    float* op = out + ((((size_t)b * 2 * CO + half * CO) * OH + oh) * OW) + lane;
    #pragma unroll 8
    for (int oo = 0; oo < CO / 8; oo++) {
        int o = oo * 8 + j;
        uint4 wv0 = sw4[o * 2 + 0];
        uint4 wv1 = sw4[o * 2 + 1];
        int s = __popc(a0 ^ wv0.x) + __popc(a1 ^ wv0.y)
              + __popc(a2 ^ wv0.z) + __popc(a3 ^ wv0.w)
              + __popc(a4 ^ wv1.x) + __popc(a5 ^ wv1.y)
              + __popc(a6 ^ wv1.z) + __popc(a7 ^ wv1.w);
        op[(size_t)o * (OH * OW)] = (float)(C - 2 * s);
    }
}

// ============================================================
extern "C" void kernel_launch(void* const* d_in, const int* in_sizes, int n_in,
                              void* d_out, int out_size) {
    const float* x     = (const float*)d_in[0];
    const float* gamma = (const float*)d_in[1];
    const float* beta  = (const float*)d_in[2];
    const float* w1    = (const float*)d_in[3];
    const float* w2    = (const float*)d_in[4];
    float* out = (float*)d_out;

    stats_wpack_kernel<<<1088, 256>>>(x, w1, w2, gamma, beta);

    // PDL launch of fused: blocks get scheduled while stats drains;
    // gridDependencySynchronize inside preserves the data dependency.
    cudaLaunchConfig_t cfg = {};
    cfg.gridDim  = dim3(OH, B, 2);
    cfg.blockDim = dim3(256, 1, 1);
    cudaLaunchAttribute attrs[1];
    attrs[0].id = cudaLaunchAttributeProgrammaticStreamSerialization;
    attrs[0].val.programmaticStreamSerializationAllowed = 1;
    cfg.attrs = attrs;
    cfg.numAttrs = 1;
    cudaError_t e = cudaLaunchKernelEx(&cfg, fused_kernel, x, out);
    if (e != cudaSuccess) {
        (void)cudaGetLastError();   // clear; fall back to plain launch
        fused_kernel<<<dim3(OH, B, 2), 256>>>(x, out);
    }
}

// round 16
// speedup vs baseline: 1.1103x; 1.0373x over previous
#include <cuda_runtime.h>
#include <cstdint>

// Problem constants
#define B   32
#define C   256
#define H   56
#define W   56
#define OH  28
#define OW  28
#define CO  256           // outputs per half
#define NW  8             // 256 bits -> 8 uint32 words
#define NELEM_PER_C (B*H*W)  // 100352

// -------- device scratch (no allocations allowed) --------
__device__ float    g_partial[C][B][2];          // per (channel, batch): sum, sumsq
__device__ float    g_lo[C];                     // binarize window: +1 iff lo <= v <= hi
__device__ float    g_hi[C];
__device__ int      g_fast;                      // 1 if all gamma > 0 (lo-only compare)
__device__ unsigned g_wpack[2*CO][NW];           // rows 0..255 = w1, 256..511 = w2
__device__ unsigned g_count;                     // stats-block arrival counter (reset each run)

// ============================================================
// Kernel 1: stats partials (one warp per (b,c) plane) + weight pack
// + LAST-BLOCK threshold finalize.
// PDL trigger at the TOP: secondary grid may co-schedule immediately as
// blocks retire; its gridDependencySynchronize still waits for this whole
// grid (incl. the finalize) before consuming g_lo/g_fast/g_wpack.
// ============================================================
__global__ __launch_bounds__(256) void stats_wpack_kernel(const float* __restrict__ x,
                                                          const float* __restrict__ w1,
                                                          const float* __restrict__ w2,
                                                          const float* __restrict__ gamma,
                                                          const float* __restrict__ beta) {
    cudaTriggerProgrammaticLaunchCompletion();

    int lane = threadIdx.x & 31;
    if (blockIdx.x >= 1024) {
        int warp = ((blockIdx.x - 1024) * 256 + threadIdx.x) >> 5;   // 0..511
        const float* w = (warp < CO) ? (w1 + (size_t)warp * C)
                                     : (w2 + (size_t)(warp - CO) * C);
        #pragma unroll
        for (int j = 0; j < NW; j++) {
            float v = w[j * 32 + lane];
            unsigned m = __ballot_sync(0xffffffffu, v >= 0.f);
            if (lane == 0) g_wpack[warp][j] = m;
        }
        return;
    }
    int wid = (blockIdx.x * 256 + threadIdx.x) >> 5;  // plane 0..8191
    int b = wid >> 8, c = wid & 255;
    const float4* p = reinterpret_cast<const float4*>(x + ((size_t)b * C + c) * (H * W));
    float s0 = 0.f, s1 = 0.f, q0 = 0.f, q1 = 0.f;
    #pragma unroll 8
    for (int it = 0; it < 24; it++) {
        float4 v = p[lane + it * 32];
        s0 += v.x + v.y;
        s1 += v.z + v.w;
        q0 += v.x * v.x + v.y * v.y;
        q1 += v.z * v.z + v.w * v.w;
    }
    if (lane < 16) {
        float4 v = p[lane + 768];
        s0 += v.x + v.y;
        s1 += v.z + v.w;
        q0 += v.x * v.x + v.y * v.y;
        q1 += v.z * v.z + v.w * v.w;
    }
    float s = s0 + s1, q = q0 + q1;
    #pragma unroll
    for (int o = 16; o > 0; o >>= 1) {
        s += __shfl_down_sync(0xffffffffu, s, o);
        q += __shfl_down_sync(0xffffffffu, q, o);
    }
    if (lane == 0) {
        g_partial[c][b][0] = s;
        g_partial[c][b][1] = q;
    }

    // ---- last-arriving stats block finalizes thresholds ----
    __threadfence();
    __shared__ int is_last;
    if (threadIdx.x == 0)
        is_last = (atomicAdd(&g_count, 1u) == 1023u);
    __syncthreads();
    if (!is_last) return;

    {
        int c2 = threadIdx.x;                     // 256 threads = 256 channels
        float ss = 0.f, sq = 0.f;
        #pragma unroll
        for (int k = 0; k < B; k++) { ss += g_partial[c2][k][0]; sq += g_partial[c2][k][1]; }
        const float N = (float)NELEM_PER_C;
        float mean = ss / N;
        float var  = sq / N - mean * mean;
        if (var < 0.f) var = 0.f;
        float inv = rsqrtf(var + 1e-5f);
        float g = gamma[c2], bt = beta[c2];
        const float INF = __int_as_float(0x7f800000);
        float lo, hi;
        if (g > 0.f)      { lo = mean - bt / (inv * g); hi =  INF; }
        else if (g < 0.f) { hi = mean - bt / (inv * g); lo = -INF; }
        else if (bt >= 0.f) { lo = -INF; hi =  INF; }
        else                { lo =  INF; hi = -INF; }
        g_lo[c2] = lo;
        g_hi[c2] = hi;

        __shared__ int sflag;
        if (threadIdx.x == 0) sflag = 1;
        __syncthreads();
        unsigned warp_ok = __ballot_sync(0xffffffffu, g > 0.f);
        if ((threadIdx.x & 31) == 0 && warp_ok != 0xffffffffu) atomicAnd(&sflag, 0);
        __syncthreads();
        if (threadIdx.x == 0) {
            g_fast = sflag;
            g_count = 0;          // reset for next graph replay
        }
    }
}

// ============================================================
// Kernel 2 (FUSED): preload x BEFORE the PDL dependency sync, then
// binarize+pack into smem, then XNOR-popcount GEMM (r12 structure).
// - x loads are independent of kernel 1 -> issued pre-sync, overlapping
//   stats' tail on otherwise-idle DRAM cycles.
// - b reversed: earliest fused blocks read the x region stats is touching
//   concurrently -> L2 hits during the overlap window.
// ============================================================
__global__ __launch_bounds__(256) void fused_kernel(const float* __restrict__ x,
                                                    float* __restrict__ out) {
    int oh = blockIdx.x, b = (B - 1) - blockIdx.y, half = blockIdx.z;
    int j    = threadIdx.x >> 5;
    int lane = threadIdx.x & 31;
    int h = 2 * oh + half;

    __shared__ uint4 sa4[OW * NW / 4];   // 896 B packed activations
    __shared__ uint4 sw4[CO * NW / 4];   // 8 KB packed weights (this half)
    unsigned* sa = reinterpret_cast<unsigned*>(sa4);

    // ---- pre-sync: issue ALL x loads (no kernel-1 dependency) ----
    float v[32];
    {
        const size_t rowstep = (size_t)H * W;
        int k = lane < OW ? lane : OW - 1;            // clamp so all lanes can shfl
        const float* base = x + (((size_t)b * C + j * 32) * H + h) * W;
        #pragma unroll
        for (int r = 0; r < 32; r++) {
            float2 t = __ldcg(reinterpret_cast<const float2*>(base + r * rowstep) + k);
            v[r] = half ? t.y : t.x;
        }
    }

    // ---- wait for stats_wpack_kernel's memory (thresholds, weights) ----
    cudaGridDependencySynchronize();

    // ---- Phase A: compare + register-pack (data already in regs) ----
    {
        unsigned bits = 0;
        if (g_fast) {
            float lo_mine = g_lo[j * 32 + lane];      // one value per lane
            #pragma unroll
            for (int r = 0; r < 32; r++) {
                float lo_r = __shfl_sync(0xffffffffu, lo_mine, r);
                bits |= (v[r] >= lo_r ? 1u : 0u) << r;
            }
        } else {
            float lo_mine = g_lo[j * 32 + lane];
            float hi_mine = g_hi[j * 32 + lane];
            #pragma unroll
            for (int r = 0; r < 32; r++) {
                float lo_r = __shfl_sync(0xffffffffu, lo_mine, r);
                float hi_r = __shfl_sync(0xffffffffu, hi_mine, r);
                bool pred = (v[r] >= lo_r) && (v[r] <= hi_r);
                bits |= (pred ? 1u : 0u) << r;
            }
        }
        if (lane < OW) sa[lane * NW + j] = bits;
    }

    // ---- stage weights (L2-hot after first wave) ----
    {
        const uint4* wsrc = reinterpret_cast<const uint4*>(&g_wpack[half * CO][0]);
        #pragma unroll
        for (int i = 0; i < (CO * NW / 4) / 256; i++)
            sw4[i * 256 + threadIdx.x] = wsrc[i * 256 + threadIdx.x];
    }
    __syncthreads();

    // ---- Phase B: popcount GEMM (vector LDS) ----
    if (lane >= OW) return;

    uint4 av0 = sa4[lane * 2 + 0];
    uint4 av1 = sa4[lane * 2 + 1];
    unsigned a0 = av0.x, a1 = av0.y, a2 = av0.z, a3 = av0.w;
    unsigned a4 = av1.x, a5 = av1.y, a6 = av1.z, a7 = av1.w;

    float* op = out + ((((size_t)b * 2 * CO + half * CO) * OH + oh) * OW) + lane;
    #pragma unroll 8
    for (int oo = 0; oo < CO / 8; oo++) {
        int o = oo * 8 + j;
        uint4 wv0 = sw4[o * 2 + 0];
        uint4 wv1 = sw4[o * 2 + 1];
        int s = __popc(a0 ^ wv0.x) + __popc(a1 ^ wv0.y)
              + __popc(a2 ^ wv0.z) + __popc(a3 ^ wv0.w)
              + __popc(a4 ^ wv1.x) + __popc(a5 ^ wv1.y)
              + __popc(a6 ^ wv1.z) + __popc(a7 ^ wv1.w);
        op[(size_t)o * (OH * OW)] = (float)(C - 2 * s);
    }
}

// ============================================================
extern "C" void kernel_launch(void* const* d_in, const int* in_sizes, int n_in,
                              void* d_out, int out_size) {
    const float* x     = (const float*)d_in[0];
    const float* gamma = (const float*)d_in[1];
    const float* beta  = (const float*)d_in[2];
    const float* w1    = (const float*)d_in[3];
    const float* w2    = (const float*)d_in[4];
    float* out = (float*)d_out;

    stats_wpack_kernel<<<1088, 256>>>(x, w1, w2, gamma, beta);

    // PDL launch of fused: blocks co-schedule as stats blocks retire and
    // preload x; gridDependencySynchronize preserves the data dependency.
    cudaLaunchConfig_t cfg = {};
    cfg.gridDim  = dim3(OH, B, 2);
    cfg.blockDim = dim3(256, 1, 1);
    cudaLaunchAttribute attrs[1];
    attrs[0].id = cudaLaunchAttributeProgrammaticStreamSerialization;
    attrs[0].val.programmaticStreamSerializationAllowed = 1;
    cfg.attrs = attrs;
    cfg.numAttrs = 1;
    cudaError_t e = cudaLaunchKernelEx(&cfg, fused_kernel, x, out);
    if (e != cudaSuccess) {
        (void)cudaGetLastError();   // clear; fall back to plain launch
        fused_kernel<<<dim3(OH, B, 2), 256>>>(x, out);
    }
}